// round 1
// baseline (speedup 1.0000x reference)
#include <cuda_runtime.h>
#include <cstdint>

// Problem constants (fixed shapes from setup_inputs)
#define BB    16
#define DC    16
#define ND    1024
#define CIN   64
#define COUT  128
#define NN    4096
#define KW    7
#define FDIM  (CIN*KW)      // 448
#define LTILE 64
#define FCH   32
#define THREADS 256

// Scratch (device globals; no allocation allowed)
__device__ float g_z[BB*CIN*ND];        // 4 MB  : low-res conv result
__device__ float g_y[BB*CIN*NN];        // 16 MB : pre-norm signal
__device__ float g_scale[BB*CIN];
__device__ float g_shift[BB*CIN];
__device__ float g_wT[FDIM*COUT];       // fc_w transposed [f][o]

// ---------------- packed fp32x2 helpers (Blackwell) ----------------
__device__ __forceinline__ unsigned long long ffma2(unsigned long long a,
                                                    unsigned long long b,
                                                    unsigned long long c) {
    unsigned long long d;
    asm("fma.rn.f32x2 %0, %1, %2, %3;" : "=l"(d) : "l"(a), "l"(b), "l"(c));
    return d;
}
__device__ __forceinline__ unsigned long long packdup(float v) {
    unsigned long long r;
    asm("mov.b64 %0, {%1, %1};" : "=l"(r) : "f"(v));
    return r;
}
__device__ __forceinline__ float2 unpack2(unsigned long long a) {
    float2 r;
    asm("mov.b64 {%0, %1}, %2;" : "=f"(r.x), "=f"(r.y) : "l"(a));
    return r;
}

// ---------------- kernel 1: z[b,c,m] = sum_d conv_w[c,d]*deep[b,d,m] ----------------
__global__ void k_z(const float* __restrict__ deep, const float* __restrict__ conv_w) {
    int idx = blockIdx.x * blockDim.x + threadIdx.x;
    if (idx >= BB*CIN*ND) return;
    int m = idx & (ND-1);
    int c = (idx >> 10) & (CIN-1);
    int b = idx >> 16;
    const float* dp = deep + (size_t)b*DC*ND + m;
    float acc = 0.f;
    #pragma unroll
    for (int d = 0; d < DC; ++d)
        acc += __ldg(&conv_w[c*DC + d]) * dp[(size_t)d*ND];
    g_z[idx] = acc;
}

// ---------------- kernel 2: transpose fc_w -> [f][o] ----------------
__global__ void k_wT(const float* __restrict__ fc_w) {
    int idx = blockIdx.x * blockDim.x + threadIdx.x;
    if (idx >= FDIM*COUT) return;
    int o = idx & (COUT-1);
    int f = idx >> 7;
    g_wT[idx] = fc_w[o*FDIM + f];
}

// ---------------- kernel 3: y = lerp(z)+bias, per-(b,c) mean/var -> scale/shift ----------------
__global__ void k_stats(const float* __restrict__ conv_b) {
    __shared__ float sz[ND];
    __shared__ float red1[8], red2[8];
    int bc  = blockIdx.x;            // b*CIN + c
    int c   = bc & (CIN-1);
    int tid = threadIdx.x;
    const float* zrow = g_z + (size_t)bc*ND;
    for (int i = tid; i < ND; i += THREADS) sz[i] = zrow[i];
    __syncthreads();
    float bias = conv_b[c];
    float s1 = 0.f, s2 = 0.f;
    float* yrow = g_y + (size_t)bc*NN;
    for (int n = tid; n < NN; n += THREADS) {
        // src = (n+0.5)*(1024/4096) - 0.5 ; exact in fp32
        float src = 0.25f*(float)n - 0.375f;
        src = fminf(fmaxf(src, 0.f), (float)(ND-1));
        int lo = (int)src;                 // src >= 0
        int hi = min(lo + 1, ND-1);
        float w = src - (float)lo;
        float v = sz[lo]*(1.f - w) + sz[hi]*w + bias;
        yrow[n] = v;
        s1 += v; s2 += v*v;
    }
    #pragma unroll
    for (int off = 16; off; off >>= 1) {
        s1 += __shfl_down_sync(0xffffffffu, s1, off);
        s2 += __shfl_down_sync(0xffffffffu, s2, off);
    }
    if ((tid & 31) == 0) { red1[tid>>5] = s1; red2[tid>>5] = s2; }
    __syncthreads();
    if (tid == 0) {
        float t1 = 0.f, t2 = 0.f;
        #pragma unroll
        for (int i = 0; i < 8; ++i) { t1 += red1[i]; t2 += red2[i]; }
        float mean = t1 / (float)NN;
        float var  = (t2 - (float)NN*mean*mean) / (float)(NN-1);
        float sc   = 0.5f / (var + 1e-9f);     // GAMA=0.5
        g_scale[bc] = sc;
        g_shift[bc] = -sc * mean;
    }
}

// ---------------- kernel 4: fused loss-modulated unfold + GEMM ----------------
// grid: (NN/LTILE, BB); block: 256 threads
// smem: m[448][64] | w[32][128] | x[64][72] | xs[64][72]
__global__ __launch_bounds__(THREADS, 1)
void k_main(const float* __restrict__ x, float* __restrict__ out) {
    extern __shared__ float sm[];
    float* sm_m  = sm;                        // 448*64
    float* sm_w  = sm_m + FDIM*LTILE;         // 32*128
    float* sm_x  = sm_w + FCH*COUT;           // 64*72
    float* sm_xs = sm_x + CIN*72;             // 64*72

    const int b   = blockIdx.y;
    const int l0  = blockIdx.x * LTILE;
    const int tid = threadIdx.x;

    // ---- stage x / xs tiles (reflect padding), positions p = l0-3+i, i in [0,70) ----
    for (int t = tid; t < CIN*70; t += THREADS) {
        int i = t % 70;
        int c = t / 70;
        int p = l0 - 3 + i;
        if (p < 0)   p = -p;
        if (p >= NN) p = 2*NN - 2 - p;
        int bc = b*CIN + c;
        sm_x [c*72 + i] = x[(size_t)bc*NN + p];
        sm_xs[c*72 + i] = g_scale[bc] * g_y[(size_t)bc*NN + p] + g_shift[bc];
    }
    __syncthreads();

    // ---- build m[l, c*7+k] = alpha * sech2(|xs(l+k-3)-xs(l)|) * x(l+k-3) ----
    for (int t = tid; t < CIN*LTILE; t += THREADS) {
        int li = t & (LTILE-1);
        int c  = t >> 6;
        const float* xs = sm_xs + c*72 + li;
        const float* xx = sm_x  + c*72 + li;
        float center = xs[3];
        float p[KW];
        float ssum = 0.f;
        #pragma unroll
        for (int k = 0; k < KW; ++k) {
            float s;
            if (k == 3) {
                s = 1.f;
            } else {
                float d = fabsf(xs[k] - center);
                float u = __expf(-2.f * d);
                float v = 1.f + u;
                s = 4.f * u / (v * v);       // sech^2(d) = 1 - tanh^2(d)
            }
            ssum += s;
            p[k] = s * xx[k];
        }
        float alpha = 1.f / ssum;
        #pragma unroll
        for (int k = 0; k < KW; ++k)
            sm_m[(c*KW + k)*LTILE + li] = alpha * p[k];
    }
    __syncthreads();

    // ---- GEMM: out[o, l] = sum_f m[l,f] * wT[f,o]; thread tile 8l x 4o (l packed) ----
    const int tx = tid & 7;      // l group: l = l0 + tx*8 + 0..7
    const int ty = tid >> 3;     // o group: o = ty*4 + 0..3
    unsigned long long acc[4][4];
    #pragma unroll
    for (int io = 0; io < 4; ++io)
        #pragma unroll
        for (int lp = 0; lp < 4; ++lp) acc[io][lp] = 0ull;

    for (int fc = 0; fc < FDIM; fc += FCH) {
        for (int t = tid; t < FCH*COUT; t += THREADS)
            sm_w[t] = g_wT[fc*COUT + t];
        __syncthreads();
        #pragma unroll 4
        for (int fi = 0; fi < FCH; ++fi) {
            const float* mrow = sm_m + (fc + fi)*LTILE + tx*8;
            ulonglong2 mv0 = *(const ulonglong2*)(mrow);
            ulonglong2 mv1 = *(const ulonglong2*)(mrow + 4);
            float4 wv = *(const float4*)(sm_w + fi*COUT + ty*4);
            unsigned long long w0 = packdup(wv.x);
            unsigned long long w1 = packdup(wv.y);
            unsigned long long w2 = packdup(wv.z);
            unsigned long long w3 = packdup(wv.w);
            acc[0][0] = ffma2(mv0.x, w0, acc[0][0]);
            acc[0][1] = ffma2(mv0.y, w0, acc[0][1]);
            acc[0][2] = ffma2(mv1.x, w0, acc[0][2]);
            acc[0][3] = ffma2(mv1.y, w0, acc[0][3]);
            acc[1][0] = ffma2(mv0.x, w1, acc[1][0]);
            acc[1][1] = ffma2(mv0.y, w1, acc[1][1]);
            acc[1][2] = ffma2(mv1.x, w1, acc[1][2]);
            acc[1][3] = ffma2(mv1.y, w1, acc[1][3]);
            acc[2][0] = ffma2(mv0.x, w2, acc[2][0]);
            acc[2][1] = ffma2(mv0.y, w2, acc[2][1]);
            acc[2][2] = ffma2(mv1.x, w2, acc[2][2]);
            acc[2][3] = ffma2(mv1.y, w2, acc[2][3]);
            acc[3][0] = ffma2(mv0.x, w3, acc[3][0]);
            acc[3][1] = ffma2(mv0.y, w3, acc[3][1]);
            acc[3][2] = ffma2(mv1.x, w3, acc[3][2]);
            acc[3][3] = ffma2(mv1.y, w3, acc[3][3]);
        }
        __syncthreads();
    }

    // ---- write out[b, o, l] ----
    float* outp = out + (size_t)b*COUT*NN + l0 + tx*8;
    #pragma unroll
    for (int io = 0; io < 4; ++io) {
        int o = ty*4 + io;
        float2 u0 = unpack2(acc[io][0]);
        float2 u1 = unpack2(acc[io][1]);
        float2 u2 = unpack2(acc[io][2]);
        float2 u3 = unpack2(acc[io][3]);
        float4 v0 = make_float4(u0.x, u0.y, u1.x, u1.y);
        float4 v1 = make_float4(u2.x, u2.y, u3.x, u3.y);
        *(float4*)(outp + (size_t)o*NN)     = v0;
        *(float4*)(outp + (size_t)o*NN + 4) = v1;
    }
}

// ---------------- launch ----------------
extern "C" void kernel_launch(void* const* d_in, const int* in_sizes, int n_in,
                              void* d_out, int out_size) {
    const float* deep   = (const float*)d_in[0];
    const float* x      = (const float*)d_in[1];
    const float* conv_w = (const float*)d_in[2];
    const float* conv_b = (const float*)d_in[3];
    const float* fc_w   = (const float*)d_in[4];
    float* out = (float*)d_out;

    static const int SMEM_MAIN = (FDIM*LTILE + FCH*COUT + 2*CIN*72) * (int)sizeof(float);
    cudaFuncSetAttribute(k_main, cudaFuncAttributeMaxDynamicSharedMemorySize, SMEM_MAIN);

    k_wT   <<<(FDIM*COUT + 255)/256, 256>>>(fc_w);
    k_z    <<<(BB*CIN*ND + 255)/256, 256>>>(deep, conv_w);
    k_stats<<<BB*CIN, THREADS>>>(conv_b);
    k_main <<<dim3(NN/LTILE, BB), THREADS, SMEM_MAIN>>>(x, out);
}

// round 3
// speedup vs baseline: 3.1210x; 3.1210x over previous
#include <cuda_runtime.h>
#include <cuda_bf16.h>
#include <cstdint>

// Fixed problem shapes
#define BB    16
#define DC    16
#define ND    1024
#define CIN   64
#define COUT  128
#define NN    4096
#define KW    7
#define LT    128            // l-tile per CTA
#define NCH   8              // K chunks (8 channels each)
#define THREADS 256

// Scratch (device globals; no allocation allowed)
__device__ float g_z[BB*CIN*ND];
__device__ float g_y[BB*CIN*NN];
__device__ float g_scale[BB*CIN];
__device__ float g_shift[BB*CIN];
__device__ __align__(16) __nv_bfloat16 g_wHi[NCH*COUT*64];   // [ch][o][col], col=cc*8+k
__device__ __align__(16) __nv_bfloat16 g_wLo[NCH*COUT*64];

// ---------------- smem layout (bytes) ----------------
// rows of 64 bf16 padded to 72 (144B stride) -> conflict-free ldmatrix
#define ROWB   144
#define OFF_X      0
#define OFF_XS     (CIN*136*4)                 // 34816
#define OFF_ST0    (2*CIN*136*4)               // 69632
#define STAGE_BYTES (4*COUT*ROWB)              // 73728
#define OFF_ST1    (OFF_ST0 + STAGE_BYTES)
#define SMEM_TOTAL (OFF_ST1 + STAGE_BYTES)     // 217088
#define T_WH   0
#define T_WL   (COUT*ROWB)                     // 18432
#define T_MH   (2*COUT*ROWB)
#define T_ML   (3*COUT*ROWB)

__device__ __forceinline__ uint32_t smem_u32(const void* p) {
    uint32_t a;
    asm("{ .reg .u64 t; cvta.to.shared.u64 t, %1; cvt.u32.u64 %0, t; }" : "=r"(a) : "l"(p));
    return a;
}
// pack(first, second) -> bf16x2, first in bits[15:0] (memory order)
__device__ __forceinline__ uint32_t packbf(float a0, float a1) {
    uint32_t r;
    asm("cvt.rn.bf16x2.f32 %0, %1, %2;" : "=r"(r) : "f"(a1), "f"(a0));
    return r;
}
#define LDSM4(r, a) \
    asm volatile("ldmatrix.sync.aligned.m8n8.x4.shared.b16 {%0,%1,%2,%3}, [%4];" \
        : "=r"((r)[0]), "=r"((r)[1]), "=r"((r)[2]), "=r"((r)[3]) : "r"(a))
#define MMA(d, a, b0, b1) \
    asm volatile("mma.sync.aligned.m16n8k16.row.col.f32.bf16.bf16.f32 " \
        "{%0,%1,%2,%3},{%4,%5,%6,%7},{%8,%9},{%0,%1,%2,%3};" \
        : "+f"((d)[0]), "+f"((d)[1]), "+f"((d)[2]), "+f"((d)[3]) \
        : "r"((a)[0]), "r"((a)[1]), "r"((a)[2]), "r"((a)[3]), "r"(b0), "r"(b1))

// ---------------- kernel 1: z[b,c,m] = sum_d conv_w[c,d]*deep[b,d,m] ----------------
__global__ void k_z(const float* __restrict__ deep, const float* __restrict__ conv_w) {
    int idx = blockIdx.x * blockDim.x + threadIdx.x;
    if (idx >= BB*CIN*ND) return;
    int m = idx & (ND-1);
    int c = (idx >> 10) & (CIN-1);
    int b = idx >> 16;
    const float* dp = deep + (size_t)b*DC*ND + m;
    float acc = 0.f;
    #pragma unroll
    for (int d = 0; d < DC; ++d)
        acc += __ldg(&conv_w[c*DC + d]) * dp[(size_t)d*ND];
    g_z[idx] = acc;
}

// ---------------- kernel 2: split fc_w into bf16 hi/lo chunk tiles ----------------
__global__ void k_wsplit(const float* __restrict__ fc_w) {
    int idx = blockIdx.x * blockDim.x + threadIdx.x;
    if (idx >= NCH*COUT*64) return;
    int ch  = idx >> 13;
    int o   = (idx >> 6) & 127;
    int col = idx & 63;
    int cc = col >> 3, k = col & 7;
    float v = 0.f;
    if (k < KW) v = fc_w[o*(CIN*KW) + (ch*8 + cc)*KW + k];
    __nv_bfloat16 hi = __float2bfloat16(v);
    __nv_bfloat16 lo = __float2bfloat16(v - __bfloat162float(hi));
    g_wHi[idx] = hi;
    g_wLo[idx] = lo;
}

// ---------------- kernel 3: y = lerp(z)+bias, per-(b,c) scale/shift ----------------
__global__ void k_stats(const float* __restrict__ conv_b) {
    __shared__ float sz[ND];
    __shared__ float red1[8], red2[8];
    int bc  = blockIdx.x;
    int c   = bc & (CIN-1);
    int tid = threadIdx.x;
    const float* zrow = g_z + (size_t)bc*ND;
    for (int i = tid; i < ND; i += THREADS) sz[i] = zrow[i];
    __syncthreads();
    float bias = conv_b[c];
    float s1 = 0.f, s2 = 0.f;
    float* yrow = g_y + (size_t)bc*NN;
    for (int n = tid; n < NN; n += THREADS) {
        float src = 0.25f*(float)n - 0.375f;
        src = fminf(fmaxf(src, 0.f), (float)(ND-1));
        int lo = (int)src;
        int hi = min(lo + 1, ND-1);
        float w = src - (float)lo;
        float v = sz[lo]*(1.f - w) + sz[hi]*w + bias;
        yrow[n] = v;
        s1 += v; s2 += v*v;
    }
    #pragma unroll
    for (int off = 16; off; off >>= 1) {
        s1 += __shfl_down_sync(0xffffffffu, s1, off);
        s2 += __shfl_down_sync(0xffffffffu, s2, off);
    }
    if ((tid & 31) == 0) { red1[tid>>5] = s1; red2[tid>>5] = s2; }
    __syncthreads();
    if (tid == 0) {
        float t1 = 0.f, t2 = 0.f;
        #pragma unroll
        for (int i = 0; i < 8; ++i) { t1 += red1[i]; t2 += red2[i]; }
        float mean = t1 / (float)NN;
        float var  = (t2 - (float)NN*mean*mean) / (float)(NN-1);
        float sc   = 0.5f / (var + 1e-9f);
        g_scale[bc] = sc;
        g_shift[bc] = -sc * mean;
    }
}

// ---------------- helpers for k_tc ----------------
__device__ __forceinline__ void load_w_chunk(char* stage, int ch, int tid) {
    const uint4* srcH = (const uint4*)(g_wHi + (size_t)ch*COUT*64);
    const uint4* srcL = (const uint4*)(g_wLo + (size_t)ch*COUT*64);
    #pragma unroll
    for (int j = 0; j < 4; ++j) {
        int idx = tid + j*THREADS;       // 0..1023 (128 rows x 8 uint4)
        int o = idx >> 3, seg = idx & 7;
        *(uint4*)(stage + T_WH + o*ROWB + seg*16) = srcH[idx];
        *(uint4*)(stage + T_WL + o*ROWB + seg*16) = srcL[idx];
    }
}

__device__ __forceinline__ void build_m_chunk(char* stage, int ch, int tid,
                                              const float* smx, const float* smxs) {
    #pragma unroll
    for (int t4 = 0; t4 < 4; ++t4) {
        int t  = tid + t4*THREADS;       // 0..1023
        int l  = t & 127;
        int cc = t >> 7;
        int c  = ch*8 + cc;
        const float* xsp = smxs + c*136 + l;
        const float* xp  = smx  + c*136 + l;
        float ctr = xsp[3];
        float u[KW], q[KW];
        #pragma unroll
        for (int k = 0; k < KW; ++k) {
            u[k] = (k == 3) ? 1.0f : __expf(-2.0f * fabsf(xsp[k] - ctr));
            float v = 1.0f + u[k];
            q[k] = v * v;
        }
        float P[KW], S[KW];
        P[0] = 1.f;
        #pragma unroll
        for (int k = 1; k < KW; ++k) P[k] = P[k-1] * q[k-1];
        S[KW-1] = 1.f;
        #pragma unroll
        for (int k = KW-2; k >= 0; --k) S[k] = S[k+1] * q[k+1];
        float nmr[KW], den = 0.f;
        #pragma unroll
        for (int k = 0; k < KW; ++k) { nmr[k] = u[k] * P[k] * S[k]; den += nmr[k]; }
        float inv = __fdividef(1.0f, den);
        float m[8];
        #pragma unroll
        for (int k = 0; k < KW; ++k) m[k] = xp[k] * nmr[k] * inv;
        m[7] = 0.f;

        uint32_t h[4], w[4];
        #pragma unroll
        for (int j = 0; j < 4; ++j) {
            h[j] = packbf(m[2*j], m[2*j+1]);
            float f0 = __uint_as_float(h[j] << 16);
            float f1 = __uint_as_float(h[j] & 0xffff0000u);
            w[j] = packbf(m[2*j] - f0, m[2*j+1] - f1);
        }
        *(uint4*)(stage + T_MH + l*ROWB + cc*16) = make_uint4(h[0], h[1], h[2], h[3]);
        *(uint4*)(stage + T_ML + l*ROWB + cc*16) = make_uint4(w[0], w[1], w[2], w[3]);
    }
}

// ---------------- kernel 4: fused build + HMMA GEMM ----------------
// grid (NN/LT=32, BB=16), 256 threads. D[o(128) x l(128)] per CTA.
// A = W[o][k] (M=o), B = m[l][k] (N=l), 3-pass bf16 split accumulation.
__global__ __launch_bounds__(THREADS, 1)
void k_tc(const float* __restrict__ x, float* __restrict__ out) {
    extern __shared__ __align__(16) char smem[];
    const uint32_t sb = smem_u32(smem);
    const int tid  = threadIdx.x;
    const int lane = tid & 31;
    const int wid  = tid >> 5;
    const int b    = blockIdx.y;
    const int l0   = blockIdx.x * LT;

    const int m0 = (wid & 1) * 64;     // o offset for this warp
    const int n0 = (wid >> 1) * 32;    // l offset for this warp
    const uint32_t laneA = (uint32_t)((lane & 15)*ROWB + ((lane >> 4) & 1)*16);
    const uint32_t laneB = (uint32_t)(((lane & 7) + 8*((lane >> 4) & 1))*ROWB + ((lane >> 3) & 1)*16);

    // ---- stage x / xs, 64 channels x 134 positions (halo 3) ----
    float* smx  = (float*)(smem + OFF_X);
    float* smxs = (float*)(smem + OFF_XS);
    for (int t = tid; t < CIN*134; t += THREADS) {
        int c = t / 134, i = t - c*134;
        int p = l0 - 3 + i;
        if (p < 0)   p = -p;
        if (p >= NN) p = 2*NN - 2 - p;
        int bc = b*CIN + c;
        smx [c*136 + i] = x[(size_t)bc*NN + p];
        smxs[c*136 + i] = g_scale[bc] * g_y[(size_t)bc*NN + p] + g_shift[bc];
    }
    __syncthreads();

    float acc[4][4][4];
    #pragma unroll
    for (int i = 0; i < 4; ++i)
        #pragma unroll
        for (int n = 0; n < 4; ++n)
            #pragma unroll
            for (int r = 0; r < 4; ++r) acc[i][n][r] = 0.f;

    // prologue: fill stage 0
    load_w_chunk(smem + OFF_ST0, 0, tid);
    build_m_chunk(smem + OFF_ST0, 0, tid, smx, smxs);
    __syncthreads();

    for (int ch = 0; ch < NCH; ++ch) {
        char* cur = smem + (((ch & 1) == 0) ? OFF_ST0 : OFF_ST1);
        if (ch + 1 < NCH) {
            char* nxt = smem + ((((ch+1) & 1) == 0) ? OFF_ST0 : OFF_ST1);
            load_w_chunk(nxt, ch + 1, tid);
            build_m_chunk(nxt, ch + 1, tid, smx, smxs);
        }

        const uint32_t sc = sb + (uint32_t)(cur - smem);
        #pragma unroll
        for (int ks = 0; ks < 4; ++ks) {
            const uint32_t kb = (uint32_t)(ks * 32);       // 16 cols * 2B
            uint32_t ah[4][4], al[4][4], bh[2][4], bl[2][4];
            const uint32_t aH = sc + T_WH + (uint32_t)m0*ROWB + kb + laneA;
            const uint32_t aL = sc + T_WL + (uint32_t)m0*ROWB + kb + laneA;
            const uint32_t bH = sc + T_MH + (uint32_t)n0*ROWB + kb + laneB;
            const uint32_t bL = sc + T_ML + (uint32_t)n0*ROWB + kb + laneB;
            #pragma unroll
            for (int i = 0; i < 4; ++i) {
                LDSM4(ah[i], aH + i*16*ROWB);
                LDSM4(al[i], aL + i*16*ROWB);
            }
            #pragma unroll
            for (int jj = 0; jj < 2; ++jj) {
                LDSM4(bh[jj], bH + jj*16*ROWB);
                LDSM4(bl[jj], bL + jj*16*ROWB);
            }
            #pragma unroll
            for (int i = 0; i < 4; ++i) {
                #pragma unroll
                for (int n = 0; n < 4; ++n) {
                    const int jj = n >> 1, e = (n & 1)*2;
                    MMA(acc[i][n], ah[i], bh[jj][e], bh[jj][e+1]);
                    MMA(acc[i][n], ah[i], bl[jj][e], bl[jj][e+1]);
                    MMA(acc[i][n], al[i], bh[jj][e], bh[jj][e+1]);
                }
            }
        }
        __syncthreads();
    }

    // ---- epilogue: direct STG.64 ----
    const int g = lane >> 2, tq = lane & 3;
    float* outb = out + (size_t)b*COUT*NN + l0;
    #pragma unroll
    for (int i = 0; i < 4; ++i) {
        int o = m0 + i*16 + g;
        #pragma unroll
        for (int n = 0; n < 4; ++n) {
            int lp = n0 + n*8 + 2*tq;
            *(float2*)(outb + (size_t)o*NN + lp)       = make_float2(acc[i][n][0], acc[i][n][1]);
            *(float2*)(outb + (size_t)(o+8)*NN + lp)   = make_float2(acc[i][n][2], acc[i][n][3]);
        }
    }
}

// ---------------- launch ----------------
extern "C" void kernel_launch(void* const* d_in, const int* in_sizes, int n_in,
                              void* d_out, int out_size) {
    const float* deep   = (const float*)d_in[0];
    const float* x      = (const float*)d_in[1];
    const float* conv_w = (const float*)d_in[2];
    const float* conv_b = (const float*)d_in[3];
    const float* fc_w   = (const float*)d_in[4];
    float* out = (float*)d_out;

    cudaFuncSetAttribute(k_tc, cudaFuncAttributeMaxDynamicSharedMemorySize, SMEM_TOTAL);

    k_wsplit<<<(NCH*COUT*64 + 255)/256, 256>>>(fc_w);
    k_z     <<<(BB*CIN*ND + 255)/256, 256>>>(deep, conv_w);
    k_stats <<<BB*CIN, THREADS>>>(conv_b);
    k_tc    <<<dim3(NN/LT, BB), THREADS, SMEM_TOTAL>>>(x, out);
}

// round 4
// speedup vs baseline: 3.6100x; 1.1567x over previous
#include <cuda_runtime.h>
#include <cuda_fp16.h>
#include <cstdint>

// Fixed problem shapes
#define BB    16
#define DC    16
#define ND    1024
#define CIN   64
#define COUT  128
#define NN    4096
#define KW    7
#define LT    128            // l-tile per CTA
#define NCH   8              // K chunks (8 channels each)
#define NTHR  384            // 8 consumer warps + 4 producer warps

// Scratch (device globals; no allocation allowed)
__device__ float g_z[BB*CIN*ND];
__device__ float g_y[BB*CIN*NN];
__device__ float g_scale[BB*CIN];
__device__ float g_shift[BB*CIN];
__device__ __align__(16) __half g_wHi[NCH*COUT*64];   // [ch][o][col], col=cc*8+k
__device__ __align__(16) __half g_wLo[NCH*COUT*64];

// ---------------- smem layout (bytes) ----------------
#define ROWB   144                              // 64 cols bf16/fp16 padded to 72 (conflict-free)
#define OFF_X      0
#define OFF_XS     (CIN*136*4)                  // 34816
#define OFF_ST0    (2*CIN*136*4)                // 69632 (1024-aligned)
#define T_WH   0
#define T_WL   (COUT*ROWB)                      // 18432
#define T_M    (2*COUT*ROWB)                    // 36864
#define STAGE_BYTES (3*COUT*ROWB)               // 55296
#define OFF_ST1    (OFF_ST0 + STAGE_BYTES)
#define SMEM_TOTAL (OFF_ST1 + STAGE_BYTES)      // 180224

// named barriers
#define BAR_FULL0  1
#define BAR_FULL1  2
#define BAR_EMPTY0 3
#define BAR_EMPTY1 4
#define BAR_PROD   5

#define BSYNC(id, n)   asm volatile("bar.sync %0, %1;"   :: "r"(id), "r"(n) : "memory")
#define BARRIVE(id, n) asm volatile("bar.arrive %0, %1;" :: "r"(id), "r"(n) : "memory")

__device__ __forceinline__ uint32_t smem_u32(const void* p) {
    uint32_t a;
    asm("{ .reg .u64 t; cvta.to.shared.u64 t, %1; cvt.u32.u64 %0, t; }" : "=r"(a) : "l"(p));
    return a;
}
// pack(first, second) -> f16x2, first in bits[15:0]
__device__ __forceinline__ uint32_t packh(float a0, float a1) {
    uint32_t r;
    asm("cvt.rn.f16x2.f32 %0, %1, %2;" : "=r"(r) : "f"(a1), "f"(a0));
    return r;
}
#define LDSM4(r, a) \
    asm volatile("ldmatrix.sync.aligned.m8n8.x4.shared.b16 {%0,%1,%2,%3}, [%4];" \
        : "=r"((r)[0]), "=r"((r)[1]), "=r"((r)[2]), "=r"((r)[3]) : "r"(a))
#define MMAH(d, a, b0, b1) \
    asm volatile("mma.sync.aligned.m16n8k16.row.col.f32.f16.f16.f32 " \
        "{%0,%1,%2,%3},{%4,%5,%6,%7},{%8,%9},{%0,%1,%2,%3};" \
        : "+f"((d)[0]), "+f"((d)[1]), "+f"((d)[2]), "+f"((d)[3]) \
        : "r"((a)[0]), "r"((a)[1]), "r"((a)[2]), "r"((a)[3]), "r"(b0), "r"(b1))

// ---------------- kernel 1: z[b,c,m] = sum_d conv_w[c,d]*deep[b,d,m] ----------------
__global__ void k_z(const float* __restrict__ deep, const float* __restrict__ conv_w) {
    int idx = blockIdx.x * blockDim.x + threadIdx.x;
    if (idx >= BB*CIN*ND) return;
    int m = idx & (ND-1);
    int c = (idx >> 10) & (CIN-1);
    int b = idx >> 16;
    const float* dp = deep + (size_t)b*DC*ND + m;
    float acc = 0.f;
    #pragma unroll
    for (int d = 0; d < DC; ++d)
        acc += __ldg(&conv_w[c*DC + d]) * dp[(size_t)d*ND];
    g_z[idx] = acc;
}

// ---------------- kernel 2: split fc_w into fp16 hi/lo chunk tiles ----------------
__global__ void k_wsplit(const float* __restrict__ fc_w) {
    int idx = blockIdx.x * blockDim.x + threadIdx.x;
    if (idx >= NCH*COUT*64) return;
    int ch  = idx >> 13;
    int o   = (idx >> 6) & 127;
    int col = idx & 63;
    int cc = col >> 3, k = col & 7;
    float v = 0.f;
    if (k < KW) v = fc_w[o*(CIN*KW) + (ch*8 + cc)*KW + k];
    __half hi = __float2half_rn(v);
    __half lo = __float2half_rn(v - __half2float(hi));
    g_wHi[idx] = hi;
    g_wLo[idx] = lo;
}

// ---------------- kernel 3: y = lerp(z)+bias, per-(b,c) scale/shift ----------------
__global__ void k_stats(const float* __restrict__ conv_b) {
    __shared__ float sz[ND];
    __shared__ float red1[8], red2[8];
    int bc  = blockIdx.x;
    int c   = bc & (CIN-1);
    int tid = threadIdx.x;
    const float* zrow = g_z + (size_t)bc*ND;
    for (int i = tid; i < ND; i += 256) sz[i] = zrow[i];
    __syncthreads();
    float bias = conv_b[c];
    float s1 = 0.f, s2 = 0.f;
    float* yrow = g_y + (size_t)bc*NN;
    for (int n = tid; n < NN; n += 256) {
        float src = 0.25f*(float)n - 0.375f;
        src = fminf(fmaxf(src, 0.f), (float)(ND-1));
        int lo = (int)src;
        int hi = min(lo + 1, ND-1);
        float w = src - (float)lo;
        float v = sz[lo]*(1.f - w) + sz[hi]*w + bias;
        yrow[n] = v;
        s1 += v; s2 += v*v;
    }
    #pragma unroll
    for (int off = 16; off; off >>= 1) {
        s1 += __shfl_down_sync(0xffffffffu, s1, off);
        s2 += __shfl_down_sync(0xffffffffu, s2, off);
    }
    if ((tid & 31) == 0) { red1[tid>>5] = s1; red2[tid>>5] = s2; }
    __syncthreads();
    if (tid == 0) {
        float t1 = 0.f, t2 = 0.f;
        #pragma unroll
        for (int i = 0; i < 8; ++i) { t1 += red1[i]; t2 += red2[i]; }
        float mean = t1 / (float)NN;
        float var  = (t2 - (float)NN*mean*mean) / (float)(NN-1);
        float sc   = 0.5f / (var + 1e-9f);
        g_scale[bc] = sc;
        g_shift[bc] = -sc * mean;
    }
}

// ---------------- kernel 4: warp-specialized fused build + HMMA GEMM ----------------
// grid (NN/LT=32, BB=16), 384 threads.
// warps 0-7: consumers (MMA). warps 8-11: producers (stage x/xs, W loads, m build).
// D[o(128) x l(128)] = sum_f W[o,f]*m[l,f], fp16 2-pass (W hi/lo split).
__global__ __launch_bounds__(NTHR, 1)
void k_tc(const float* __restrict__ x, float* __restrict__ out) {
    extern __shared__ __align__(16) char smem[];
    const uint32_t sb = smem_u32(smem);
    const int tid  = threadIdx.x;
    const int lane = tid & 31;
    const int wid  = tid >> 5;
    const int b    = blockIdx.y;
    const int l0   = blockIdx.x * LT;

    if (wid >= 8) {
        // ================= PRODUCER =================
        const int ptid = tid - 256;     // 0..127
        float* smx  = (float*)(smem + OFF_X);
        float* smxs = (float*)(smem + OFF_XS);
        // stage x / xs, 64 channels x 134 positions (halo 3)
        for (int t = ptid; t < CIN*134; t += 128) {
            int c = t / 134, i = t - c*134;
            int p = l0 - 3 + i;
            if (p < 0)   p = -p;
            if (p >= NN) p = 2*NN - 2 - p;
            int bc = b*CIN + c;
            smx [c*136 + i] = x[(size_t)bc*NN + p];
            smxs[c*136 + i] = g_scale[bc] * g_y[(size_t)bc*NN + p] + g_shift[bc];
        }
        BSYNC(BAR_PROD, 128);

        for (int ch = 0; ch < NCH; ++ch) {
            const int s = ch & 1;
            if (ch >= 2) BSYNC(s ? BAR_EMPTY1 : BAR_EMPTY0, NTHR);
            char* stage = smem + (s ? OFF_ST1 : OFF_ST0);

            // W chunk (hi + lo), 1024 uint4 each
            {
                const uint4* srcH = (const uint4*)(g_wHi + (size_t)ch*COUT*64);
                const uint4* srcL = (const uint4*)(g_wLo + (size_t)ch*COUT*64);
                #pragma unroll
                for (int j = 0; j < 8; ++j) {
                    int idx = ptid + j*128;
                    int o = idx >> 3, seg = idx & 7;
                    *(uint4*)(stage + T_WH + o*ROWB + seg*16) = srcH[idx];
                    *(uint4*)(stage + T_WL + o*ROWB + seg*16) = srcL[idx];
                }
            }
            // build m chunk: 1024 (l,cc) tasks
            #pragma unroll
            for (int t8 = 0; t8 < 8; ++t8) {
                int t  = ptid + t8*128;
                int l  = t & 127;
                int cc = t >> 7;
                int c  = ch*8 + cc;
                const float* xsp = smxs + c*136 + l;
                const float* xp  = smx  + c*136 + l;
                float ctr = xsp[3];
                float u[KW], q[KW];
                #pragma unroll
                for (int k = 0; k < KW; ++k) {
                    u[k] = (k == 3) ? 1.0f : __expf(-2.0f * fabsf(xsp[k] - ctr));
                    float v = 1.0f + u[k];
                    q[k] = v * v;
                }
                float P[KW], S[KW];
                P[0] = 1.f;
                #pragma unroll
                for (int k = 1; k < KW; ++k) P[k] = P[k-1] * q[k-1];
                S[KW-1] = 1.f;
                #pragma unroll
                for (int k = KW-2; k >= 0; --k) S[k] = S[k+1] * q[k+1];
                float nmr[KW], den = 0.f;
                #pragma unroll
                for (int k = 0; k < KW; ++k) { nmr[k] = u[k] * P[k] * S[k]; den += nmr[k]; }
                float inv = __fdividef(1.0f, den);
                float m[8];
                #pragma unroll
                for (int k = 0; k < KW; ++k) m[k] = xp[k] * nmr[k] * inv;
                m[7] = 0.f;
                uint32_t h[4];
                #pragma unroll
                for (int j = 0; j < 4; ++j) h[j] = packh(m[2*j], m[2*j+1]);
                *(uint4*)(stage + T_M + l*ROWB + cc*16) = make_uint4(h[0], h[1], h[2], h[3]);
            }
            asm volatile("membar.cta;" ::: "memory");
            BARRIVE(s ? BAR_FULL1 : BAR_FULL0, NTHR);
        }
        return;
    }

    // ================= CONSUMER =================
    const int m0 = (wid & 1) * 64;     // o offset
    const int n0 = (wid >> 1) * 32;    // l offset
    const uint32_t laneA = (uint32_t)((lane & 15)*ROWB + ((lane >> 4) & 1)*16);
    const uint32_t laneB = (uint32_t)(((lane & 7) + 8*((lane >> 4) & 1))*ROWB + ((lane >> 3) & 1)*16);

    float acc[4][4][4];
    #pragma unroll
    for (int i = 0; i < 4; ++i)
        #pragma unroll
        for (int n = 0; n < 4; ++n)
            #pragma unroll
            for (int r = 0; r < 4; ++r) acc[i][n][r] = 0.f;

    for (int ch = 0; ch < NCH; ++ch) {
        const int s = ch & 1;
        BSYNC(s ? BAR_FULL1 : BAR_FULL0, NTHR);
        const uint32_t sc = sb + (uint32_t)(s ? OFF_ST1 : OFF_ST0);
        #pragma unroll
        for (int ks = 0; ks < 4; ++ks) {
            const uint32_t kb = (uint32_t)(ks * 32);
            uint32_t ah[4][4], al[4][4], bm[2][4];
            const uint32_t aH = sc + T_WH + (uint32_t)m0*ROWB + kb + laneA;
            const uint32_t aL = sc + T_WL + (uint32_t)m0*ROWB + kb + laneA;
            const uint32_t bM = sc + T_M  + (uint32_t)n0*ROWB + kb + laneB;
            #pragma unroll
            for (int i = 0; i < 4; ++i) {
                LDSM4(ah[i], aH + i*16*ROWB);
                LDSM4(al[i], aL + i*16*ROWB);
            }
            #pragma unroll
            for (int jj = 0; jj < 2; ++jj)
                LDSM4(bm[jj], bM + jj*16*ROWB);
            #pragma unroll
            for (int i = 0; i < 4; ++i) {
                #pragma unroll
                for (int n = 0; n < 4; ++n) {
                    const int jj = n >> 1, e = (n & 1)*2;
                    MMAH(acc[i][n], ah[i], bm[jj][e], bm[jj][e+1]);
                    MMAH(acc[i][n], al[i], bm[jj][e], bm[jj][e+1]);
                }
            }
        }
        BARRIVE(s ? BAR_EMPTY1 : BAR_EMPTY0, NTHR);
    }

    // ---- epilogue: direct STG.64 ----
    const int g = lane >> 2, tq = lane & 3;
    float* outb = out + (size_t)b*COUT*NN + l0;
    #pragma unroll
    for (int i = 0; i < 4; ++i) {
        int o = m0 + i*16 + g;
        #pragma unroll
        for (int n = 0; n < 4; ++n) {
            int lp = n0 + n*8 + 2*tq;
            *(float2*)(outb + (size_t)o*NN + lp)     = make_float2(acc[i][n][0], acc[i][n][1]);
            *(float2*)(outb + (size_t)(o+8)*NN + lp) = make_float2(acc[i][n][2], acc[i][n][3]);
        }
    }
}

// ---------------- launch ----------------
extern "C" void kernel_launch(void* const* d_in, const int* in_sizes, int n_in,
                              void* d_out, int out_size) {
    const float* deep   = (const float*)d_in[0];
    const float* x      = (const float*)d_in[1];
    const float* conv_w = (const float*)d_in[2];
    const float* conv_b = (const float*)d_in[3];
    const float* fc_w   = (const float*)d_in[4];
    float* out = (float*)d_out;

    cudaFuncSetAttribute(k_tc, cudaFuncAttributeMaxDynamicSharedMemorySize, SMEM_TOTAL);

    k_wsplit<<<(NCH*COUT*64 + 255)/256, 256>>>(fc_w);
    k_z     <<<(BB*CIN*ND + 255)/256, 256>>>(deep, conv_w);
    k_stats <<<BB*CIN, 256>>>(conv_b);
    k_tc    <<<dim3(NN/LT, BB), NTHR, SMEM_TOTAL>>>(x, out);
}

// round 5
// speedup vs baseline: 3.7388x; 1.0357x over previous
#include <cuda_runtime.h>
#include <cuda_fp16.h>
#include <cstdint>

// Fixed problem shapes
#define BB    16
#define DC    16
#define ND    1024
#define CIN   64
#define COUT  128
#define NN    4096
#define KW    7
#define LT    64             // l-tile per CTA
#define NCH   8              // K chunks (8 channels each)
#define NTHR  384            // 8 consumer warps + 4 producer warps

// Scratch (device globals; no allocation allowed)
__device__ float g_z[BB*CIN*ND];
__device__ float g_y[BB*CIN*NN];
__device__ float g_scale[BB*CIN];
__device__ float g_shift[BB*CIN];
__device__ __align__(16) __half g_wH[NCH*COUT*64];   // [ch][o][col], col=cc*8+k (fp16)

// ---------------- smem layout (bytes) ----------------
#define ROWB   144                 // 64 fp16 cols padded to 72 -> conflict-free ldmatrix
#define T_W    0                   // 128 o rows  : 18432
#define T_M    18432               // 64 l rows   : 9216
#define T_X    27648               // 8 ch x 72 f : 2304
#define T_XS   29952               // 8 ch x 72 f : 2304
#define STAGE_BYTES 32768
#define SMEM_TOTAL (2*STAGE_BYTES) // 65536 -> 2 CTAs/SM

// named barriers
#define BAR_FULL0  1
#define BAR_FULL1  2
#define BAR_EMPTY0 3
#define BAR_EMPTY1 4
#define BAR_PROD   5

#define BSYNC(id, n)   asm volatile("bar.sync %0, %1;"   :: "r"(id), "r"(n) : "memory")
#define BARRIVE(id, n) asm volatile("bar.arrive %0, %1;" :: "r"(id), "r"(n) : "memory")
#define CP16(dst, src) asm volatile("cp.async.cg.shared.global [%0], [%1], 16;" :: "r"(dst), "l"(src) : "memory")
#define CPCOMMIT()     asm volatile("cp.async.commit_group;" ::: "memory")
#define CPWAIT0()      asm volatile("cp.async.wait_group 0;" ::: "memory")

__device__ __forceinline__ uint32_t smem_u32(const void* p) {
    uint32_t a;
    asm("{ .reg .u64 t; cvta.to.shared.u64 t, %1; cvt.u32.u64 %0, t; }" : "=r"(a) : "l"(p));
    return a;
}
// pack(first, second) -> f16x2, first in bits[15:0]
__device__ __forceinline__ uint32_t packh(float a0, float a1) {
    uint32_t r;
    asm("cvt.rn.f16x2.f32 %0, %1, %2;" : "=r"(r) : "f"(a1), "f"(a0));
    return r;
}
#define LDSM4(r, a) \
    asm volatile("ldmatrix.sync.aligned.m8n8.x4.shared.b16 {%0,%1,%2,%3}, [%4];" \
        : "=r"((r)[0]), "=r"((r)[1]), "=r"((r)[2]), "=r"((r)[3]) : "r"(a))
#define MMAH(d, a, b0, b1) \
    asm volatile("mma.sync.aligned.m16n8k16.row.col.f32.f16.f16.f32 " \
        "{%0,%1,%2,%3},{%4,%5,%6,%7},{%8,%9},{%0,%1,%2,%3};" \
        : "+f"((d)[0]), "+f"((d)[1]), "+f"((d)[2]), "+f"((d)[3]) \
        : "r"((a)[0]), "r"((a)[1]), "r"((a)[2]), "r"((a)[3]), "r"(b0), "r"(b1))

// ---------------- kernel 1: z[b,c,m] = sum_d conv_w[c,d]*deep[b,d,m] ----------------
__global__ void k_z(const float* __restrict__ deep, const float* __restrict__ conv_w) {
    int idx = blockIdx.x * blockDim.x + threadIdx.x;
    if (idx >= BB*CIN*ND) return;
    int m = idx & (ND-1);
    int c = (idx >> 10) & (CIN-1);
    int b = idx >> 16;
    const float* dp = deep + (size_t)b*DC*ND + m;
    float acc = 0.f;
    #pragma unroll
    for (int d = 0; d < DC; ++d)
        acc += __ldg(&conv_w[c*DC + d]) * dp[(size_t)d*ND];
    g_z[idx] = acc;
}

// ---------------- kernel 2: fc_w -> fp16 chunk tiles ----------------
__global__ void k_wsplit(const float* __restrict__ fc_w) {
    int idx = blockIdx.x * blockDim.x + threadIdx.x;
    if (idx >= NCH*COUT*64) return;
    int ch  = idx >> 13;
    int o   = (idx >> 6) & 127;
    int col = idx & 63;
    int cc = col >> 3, k = col & 7;
    float v = 0.f;
    if (k < KW) v = fc_w[o*(CIN*KW) + (ch*8 + cc)*KW + k];
    g_wH[idx] = __float2half_rn(v);
}

// ---------------- kernel 3: y = lerp(z)+bias, per-(b,c) scale/shift ----------------
__global__ void k_stats(const float* __restrict__ conv_b) {
    __shared__ float sz[ND];
    __shared__ float red1[8], red2[8];
    int bc  = blockIdx.x;
    int c   = bc & (CIN-1);
    int tid = threadIdx.x;
    const float* zrow = g_z + (size_t)bc*ND;
    for (int i = tid; i < ND; i += 256) sz[i] = zrow[i];
    __syncthreads();
    float bias = conv_b[c];
    float s1 = 0.f, s2 = 0.f;
    float* yrow = g_y + (size_t)bc*NN;
    for (int n = tid; n < NN; n += 256) {
        float src = 0.25f*(float)n - 0.375f;
        src = fminf(fmaxf(src, 0.f), (float)(ND-1));
        int lo = (int)src;
        int hi = min(lo + 1, ND-1);
        float w = src - (float)lo;
        float v = sz[lo]*(1.f - w) + sz[hi]*w + bias;
        yrow[n] = v;
        s1 += v; s2 += v*v;
    }
    #pragma unroll
    for (int off = 16; off; off >>= 1) {
        s1 += __shfl_down_sync(0xffffffffu, s1, off);
        s2 += __shfl_down_sync(0xffffffffu, s2, off);
    }
    if ((tid & 31) == 0) { red1[tid>>5] = s1; red2[tid>>5] = s2; }
    __syncthreads();
    if (tid == 0) {
        float t1 = 0.f, t2 = 0.f;
        #pragma unroll
        for (int i = 0; i < 8; ++i) { t1 += red1[i]; t2 += red2[i]; }
        float mean = t1 / (float)NN;
        float var  = (t2 - (float)NN*mean*mean) / (float)(NN-1);
        float sc   = 0.5f / (var + 1e-9f);
        g_scale[bc] = sc;
        g_shift[bc] = -sc * mean;
    }
}

// ---------------- kernel 4: warp-specialized fused build + HMMA GEMM ----------------
// grid (NN/LT=64, BB=16) = 1024 CTAs, 384 threads, 2 CTAs/SM.
// warps 0-7: consumers (MMA, warp tile 32o x 32l). warps 8-11: producers.
// D[o(128) x l(64)] = sum_f W[o,f]*m[l,f], single fp16 pass.
__global__ __launch_bounds__(NTHR, 2)
void k_tc(const float* __restrict__ x, float* __restrict__ out) {
    extern __shared__ __align__(16) char smem[];
    const uint32_t sb = smem_u32(smem);
    const int tid  = threadIdx.x;
    const int lane = tid & 31;
    const int wid  = tid >> 5;
    const int b    = blockIdx.y;
    const int l0   = blockIdx.x * LT;

    if (wid >= 8) {
        // ================= PRODUCER (4 warps) =================
        const int ptid = tid - 256;     // 0..127
        for (int ch = 0; ch < NCH; ++ch) {
            const int s = ch & 1;
            if (ch >= 2) BSYNC(s ? BAR_EMPTY1 : BAR_EMPTY0, NTHR);
            char* stage = smem + s * STAGE_BYTES;
            const uint32_t st = sb + (uint32_t)(s * STAGE_BYTES);

            // W chunk via cp.async: 1024 uint4
            {
                const char* src = (const char*)(g_wH + (size_t)ch*COUT*64);
                #pragma unroll
                for (int j = 0; j < 8; ++j) {
                    int idx = ptid + j*128;
                    int o = idx >> 3, seg = idx & 7;
                    CP16(st + T_W + (uint32_t)(o*ROWB + seg*16), src + idx*16);
                }
                CPCOMMIT();
            }
            // stage x / xs: 8 channels x 70 positions (halo 3)
            {
                float* sx  = (float*)(stage + T_X);
                float* sxs = (float*)(stage + T_XS);
                for (int t = ptid; t < 8*70; t += 128) {
                    int cc = t / 70, i = t - cc*70;
                    int p = l0 - 3 + i;
                    if (p < 0)   p = -p;
                    if (p >= NN) p = 2*NN - 2 - p;
                    int bc = b*CIN + ch*8 + cc;
                    sx [cc*72 + i] = x[(size_t)bc*NN + p];
                    sxs[cc*72 + i] = g_scale[bc] * g_y[(size_t)bc*NN + p] + g_shift[bc];
                }
            }
            BSYNC(BAR_PROD, 128);

            // build m chunk: 512 (l,cc) tasks
            const float* sx  = (const float*)(stage + T_X);
            const float* sxs = (const float*)(stage + T_XS);
            #pragma unroll 1
            for (int t4 = 0; t4 < 4; ++t4) {
                int t  = ptid + t4*128;
                int l  = t & 63;
                int cc = t >> 6;
                const float* xsp = sxs + cc*72 + l;
                const float* xp  = sx  + cc*72 + l;
                float ctr = xsp[3];
                float u[KW], q[KW];
                #pragma unroll
                for (int k = 0; k < KW; ++k) {
                    u[k] = (k == 3) ? 1.0f : __expf(-2.0f * fabsf(xsp[k] - ctr));
                    float v = 1.0f + u[k];
                    q[k] = v * v;
                }
                float P[KW], S[KW];
                P[0] = 1.f;
                #pragma unroll
                for (int k = 1; k < KW; ++k) P[k] = P[k-1] * q[k-1];
                S[KW-1] = 1.f;
                #pragma unroll
                for (int k = KW-2; k >= 0; --k) S[k] = S[k+1] * q[k+1];
                float nmr[KW], den = 0.f;
                #pragma unroll
                for (int k = 0; k < KW; ++k) { nmr[k] = u[k] * P[k] * S[k]; den += nmr[k]; }
                float inv = __fdividef(1.0f, den);
                float m[8];
                #pragma unroll
                for (int k = 0; k < KW; ++k) m[k] = xp[k] * nmr[k] * inv;
                m[7] = 0.f;
                uint32_t h[4];
                #pragma unroll
                for (int j = 0; j < 4; ++j) h[j] = packh(m[2*j], m[2*j+1]);
                *(uint4*)(stage + T_M + l*ROWB + cc*16) = make_uint4(h[0], h[1], h[2], h[3]);
            }
            CPWAIT0();
            asm volatile("membar.cta;" ::: "memory");
            BARRIVE(s ? BAR_FULL1 : BAR_FULL0, NTHR);
        }
        return;
    }

    // ================= CONSUMER (8 warps) =================
    const int m0 = (wid >> 1) * 32;    // o offset
    const int n0 = (wid & 1) * 32;     // l offset
    const uint32_t laneA = (uint32_t)((lane & 15)*ROWB + ((lane >> 4) & 1)*16);
    const uint32_t laneB = (uint32_t)(((lane & 7) + 8*((lane >> 4) & 1))*ROWB + ((lane >> 3) & 1)*16);

    float acc[2][4][4];
    #pragma unroll
    for (int i = 0; i < 2; ++i)
        #pragma unroll
        for (int n = 0; n < 4; ++n)
            #pragma unroll
            for (int r = 0; r < 4; ++r) acc[i][n][r] = 0.f;

    for (int ch = 0; ch < NCH; ++ch) {
        const int s = ch & 1;
        BSYNC(s ? BAR_FULL1 : BAR_FULL0, NTHR);
        const uint32_t sc = sb + (uint32_t)(s * STAGE_BYTES);
        #pragma unroll
        for (int ks = 0; ks < 4; ++ks) {
            const uint32_t kb = (uint32_t)(ks * 32);
            uint32_t a[2][4], bm[2][4];
            const uint32_t aW = sc + T_W + (uint32_t)m0*ROWB + kb + laneA;
            const uint32_t bM = sc + T_M + (uint32_t)n0*ROWB + kb + laneB;
            LDSM4(a[0], aW);
            LDSM4(a[1], aW + 16*ROWB);
            LDSM4(bm[0], bM);
            LDSM4(bm[1], bM + 16*ROWB);
            #pragma unroll
            for (int i = 0; i < 2; ++i) {
                #pragma unroll
                for (int n = 0; n < 4; ++n) {
                    const int jj = n >> 1, e = (n & 1)*2;
                    MMAH(acc[i][n], a[i], bm[jj][e], bm[jj][e+1]);
                }
            }
        }
        BARRIVE(s ? BAR_EMPTY1 : BAR_EMPTY0, NTHR);
    }

    // ---- epilogue: direct STG.64 ----
    const int g = lane >> 2, tq = lane & 3;
    float* outb = out + (size_t)b*COUT*NN + l0;
    #pragma unroll
    for (int i = 0; i < 2; ++i) {
        int o = m0 + i*16 + g;
        #pragma unroll
        for (int n = 0; n < 4; ++n) {
            int lp = n0 + n*8 + 2*tq;
            *(float2*)(outb + (size_t)o*NN + lp)     = make_float2(acc[i][n][0], acc[i][n][1]);
            *(float2*)(outb + (size_t)(o+8)*NN + lp) = make_float2(acc[i][n][2], acc[i][n][3]);
        }
    }
}

// ---------------- launch ----------------
extern "C" void kernel_launch(void* const* d_in, const int* in_sizes, int n_in,
                              void* d_out, int out_size) {
    const float* deep   = (const float*)d_in[0];
    const float* x      = (const float*)d_in[1];
    const float* conv_w = (const float*)d_in[2];
    const float* conv_b = (const float*)d_in[3];
    const float* fc_w   = (const float*)d_in[4];
    float* out = (float*)d_out;

    cudaFuncSetAttribute(k_tc, cudaFuncAttributeMaxDynamicSharedMemorySize, SMEM_TOTAL);

    k_wsplit<<<(NCH*COUT*64 + 255)/256, 256>>>(fc_w);
    k_z     <<<(BB*CIN*ND + 255)/256, 256>>>(deep, conv_w);
    k_stats <<<BB*CIN, 256>>>(conv_b);
    k_tc    <<<dim3(NN/LT, BB), NTHR, SMEM_TOTAL>>>(x, out);
}